// round 17
// baseline (speedup 1.0000x reference)
#include <cuda_runtime.h>
#include <cuda_fp16.h>
#include <cstdint>

// ---------------- problem constants ----------------
#define NB   32
#define C_R  32
#define C_C  32
#define C_S  64
#define NV   500
#define NT   64
#define NK   52
#define NMCOL (NB*C_C*NK)   // 53248
#define VP   512
#define HVEC (C_C*NK)       // 1664
#define CNT_PER_B (C_C*NV*NK)

// ---------------- device scratch (zero-initialized) ----------------
__device__ float  g_a1f[VP*VP];
__device__ float  g_a2f[VP*VP];
__device__ __half g_Ah[2][VP*VP];     // fp16 normalized adjacency (both sides)
__device__ __half g_B1h[2][VP*VP];
__device__ __half g_B2h[2][VP*VP];
__device__ float  g_rs[NV];
__device__ float  g_cs[NV];
__device__ __half g_swh[C_S*HVEC];
__device__ __half g_Wph[7*64*40];     // packed inception weights, SMEM-image layout
__device__ float  g_fbias[C_C];
__device__ float  g_gbias[C_C];
// rows (nodes) padded to 512; rows >=500 never written, stay zero
__device__ __half g_hh  [VP*NMCOL];
__device__ __half g_h1ah[VP*NMCOL];
__device__ __half g_h1bh[VP*NMCOL];
__device__ __half g_h2ah[VP*NMCOL];
__device__ __half g_h2bh[VP*NMCOL];
__device__ __half g_xoh[NB*C_C*NV*NK];
__device__ float  g_stats[2*NB];

// ---------------- helpers ----------------
__device__ __forceinline__ uint32_t smem_u32(const void* p){
    uint32_t a; asm("{ .reg .u64 t; cvta.to.shared.u64 t, %1; cvt.u32.u64 %0, t; }":"=r"(a):"l"(p)); return a;
}
#define CP_ASYNC16(s,g) asm volatile("cp.async.cg.shared.global [%0], [%1], 16;"::"r"(s),"l"(g))
#define CP_COMMIT()     asm volatile("cp.async.commit_group;" ::: "memory")
#define CP_WAIT1()      asm volatile("cp.async.wait_group 1;" ::: "memory")
#define CP_WAIT0()      asm volatile("cp.async.wait_group 0;" ::: "memory")

__device__ __forceinline__ void ldmx4(uint32_t* r, uint32_t addr){
    asm volatile("ldmatrix.sync.aligned.m8n8.x4.shared.b16 {%0,%1,%2,%3}, [%4];"
        : "=r"(r[0]),"=r"(r[1]),"=r"(r[2]),"=r"(r[3]) : "r"(addr));
}
__device__ __forceinline__ void ldmx4t(uint32_t* r, uint32_t addr){
    asm volatile("ldmatrix.sync.aligned.m8n8.x4.trans.shared.b16 {%0,%1,%2,%3}, [%4];"
        : "=r"(r[0]),"=r"(r[1]),"=r"(r[2]),"=r"(r[3]) : "r"(addr));
}
__device__ __forceinline__ void mma_f16(float* c, const uint32_t* a, const uint32_t* b){
    asm volatile("mma.sync.aligned.m16n8k16.row.col.f32.f16.f16.f32 "
        "{%0,%1,%2,%3}, {%4,%5,%6,%7}, {%8,%9}, {%0,%1,%2,%3};"
        : "+f"(c[0]),"+f"(c[1]),"+f"(c[2]),"+f"(c[3])
        : "r"(a[0]),"r"(a[1]),"r"(a[2]),"r"(a[3]), "r"(b[0]),"r"(b[1]));
}
__device__ __forceinline__ float fast_tanh(float z){
    float e2 = __expf(fminf(-2.f*z, 40.f));
    return __fdividef(1.f - e2, 1.f + e2);
}
__device__ __forceinline__ float fast_sig(float z){
    return __fdividef(1.f, 1.f + __expf(fminf(-z, 40.f)));
}

// ---------------- pack: fp16 inception weights, half skip weights, zero sums/stats ----------------
__global__ void pack_kernel(const float* __restrict__ fw2,const float* __restrict__ fw3,
    const float* __restrict__ fw6,const float* __restrict__ fw7,
    const float* __restrict__ fb2,const float* __restrict__ fb3,
    const float* __restrict__ fb6,const float* __restrict__ fb7,
    const float* __restrict__ gw2,const float* __restrict__ gw3,
    const float* __restrict__ gw6,const float* __restrict__ gw7,
    const float* __restrict__ gb2,const float* __restrict__ gb3,
    const float* __restrict__ gb6,const float* __restrict__ gb7,
    const float* __restrict__ skipw)
{
    int tid = threadIdx.x;
    int gtid = blockIdx.x * blockDim.x + tid;
    for (int e = gtid; e < C_S*HVEC; e += gridDim.x * blockDim.x)
        g_swh[e] = __float2half_rn(skipw[e]);
    if (blockIdx.x != 0) return;
    if (tid < 2*NB) g_stats[tid] = 0.f;
    for (int e = tid; e < 7*64*32; e += blockDim.x) {
        int j = e / 2048;
        int o = (e & 2047) >> 5;
        int i = e & 31;
        int oc = o & 31;
        int br = oc >> 3, oo = oc & 7;
        int k = (br==0)?2:(br==1)?3:(br==2)?6:7;
        int j0 = 7 - k;
        float vv = 0.f;
        if (j >= j0) {
            int si = (oo*C_R + i)*k + (j - j0);
            if (o < 32) {
                const float* fw = (br==0)?fw2:(br==1)?fw3:(br==2)?fw6:fw7;
                vv = fw[si];
            } else {
                const float* gw = (br==0)?gw2:(br==1)?gw3:(br==2)?gw6:gw7;
                vv = gw[si];
            }
        }
        g_Wph[(j*64 + o)*40 + i] = __float2half_rn(vv);
    }
    if (tid < C_C) {
        int br = tid >> 3, oo = tid & 7;
        const float* fb = (br==0)?fb2:(br==1)?fb3:(br==2)?fb6:fb7;
        const float* gb = (br==0)?gb2:(br==1)?gb3:(br==2)?gb6:gb7;
        g_fbias[tid] = fb[oo]; g_gbias[tid] = gb[oo];
    }
}

// ---------------- zero col sums (side-stream chain head) ----------------
__global__ void zerocs_kernel()
{
    int e = blockIdx.x * 256 + threadIdx.x;
    if (e < NV) g_cs[e] = 0.f;
}

// ---------------- row sums (coalesced) + col sums (atomics) ----------------
__global__ void sums_kernel(const float* __restrict__ adp)
{
    int v = blockIdx.x;
    __shared__ float red[256];
    int tid = threadIdx.x;
    float s = 0.f;
    for (int w = tid; w < NV; w += 256) {
        float val = adp[v*NV + w];
        s += val;
        atomicAdd(&g_cs[w], val);
    }
    red[tid] = s; __syncthreads();
    for (int st = 128; st > 0; st >>= 1) {
        if (tid < st) red[tid] += red[tid + st];
        __syncthreads();
    }
    if (tid == 0) g_rs[v] = red[0] + 1.f;
}

// ---------------- build a1f/a2f fp32 + fp16 A + B1 fp16 for both sides ----------------
__global__ void buildAB_kernel(const float* __restrict__ adp)
{
    __shared__ float tile[32][33];
    int tid = threadIdx.x;
    int I = blockIdx.y*32, J = blockIdx.x*32;
    #pragma unroll
    for (int l = 0; l < 4; l++) {
        int ii = (tid >> 5) + l*8, jj = tid & 31;
        int r = I + ii, c = J + jj;
        tile[ii][jj] = (r < NV && c < NV) ? adp[r*NV + c] : 0.f;
    }
    __syncthreads();
    #pragma unroll
    for (int l = 0; l < 4; l++) {
        int ii = (tid >> 5) + l*8, jj = tid & 31;
        int r = I + ii, c = J + jj;
        float a1 = 0.f;
        if (r < NV && c < NV)
            a1 = (tile[ii][jj] + (r == c ? 1.f : 0.f)) * (1.f / g_rs[r]);
        g_a1f[r*VP + c] = a1;
        g_Ah[0][r*VP + c] = __float2half_rn(a1);
        g_B1h[0][r*VP + c] = __float2half_rn(0.95f*a1 + ((r == c && r < NV) ? 0.05f : 0.f));
    }
    #pragma unroll
    for (int l = 0; l < 4; l++) {
        int ii = (tid >> 5) + l*8, jj = tid & 31;
        int rr = J + ii, cc = I + jj;      // a2f[rr][cc] = (adp[cc][rr]+d)/(cs[rr]+1)
        float a2 = 0.f;
        if (rr < NV && cc < NV)
            a2 = (tile[jj][ii] + (rr == cc ? 1.f : 0.f)) * (1.f / (g_cs[rr] + 1.f));
        g_a2f[rr*VP + cc] = a2;
        g_Ah[1][rr*VP + cc] = __float2half_rn(a2);
        g_B1h[1][rr*VP + cc] = __float2half_rn(0.95f*a2 + ((rr == cc && rr < NV) ? 0.05f : 0.f));
    }
}

// ---------------- HMMA dilated inception + gating -> fp16 h ----------------
#define XST_ROWS 80
#define XST_STRB 80
#define XST_WARP (XST_ROWS*XST_STRB)
#define WP_STRB 80
#define WP_BYTES (7*64*WP_STRB)           // 35840 B
#define INCEPT_SMEM (WP_BYTES + 4*XST_WARP + 512)
__global__ __launch_bounds__(256,2) void incept_mma(const float* __restrict__ x)
{
    extern __shared__ __align__(16) char smi[];
    uint32_t sW = smem_u32(smi);
    uint32_t sX0 = sW + WP_BYTES;
    float* fbs = (float*)(smi + WP_BYTES + 4*XST_WARP);
    float* gbs = fbs + 32;

    int tid = threadIdx.x, warp = tid >> 5, lane = tid & 31;
    int pairidx = warp >> 1, wpar = warp & 1;

    for (int e = tid; e < WP_BYTES/16; e += 256)
        *(float4*)(smi + e*16) = *(const float4*)(((const char*)g_Wph) + e*16);
    if (tid < 32) { fbs[tid] = g_fbias[tid]; gbs[tid] = g_gbias[tid]; }

    int p = blockIdx.x * 4 + pairidx;
    int n = p >> 5, b = p & 31;
    uint32_t sX = sX0 + pairidx*XST_WARP;
    {
        int tid64 = tid & 63;
        int i0 = (tid64 & 15) * 2;
        int t0 = (tid64 >> 4) * 16;
        const float* xr0 = &x[((size_t)(b*C_R + i0)*NV + n)*NT + t0];
        const float* xr1 = xr0 + (size_t)NV*NT;
        #pragma unroll
        for (int q = 0; q < 4; q++) {
            float4 v0 = *(const float4*)&xr0[q*4];
            float4 v1 = *(const float4*)&xr1[q*4];
            const float* a0 = &v0.x; const float* a1 = &v1.x;
            #pragma unroll
            for (int r = 0; r < 4; r++) {
                int t = t0 + q*4 + r;
                *(__half2*)(smi + (sX - smem_u32(smi)) + t*XST_STRB + i0*2) =
                    __floats2half2_rn(a0[r], a1[r]);
            }
        }
    }
    __syncthreads();

    float c[2][7][4];
    #pragma unroll
    for (int ml = 0; ml < 2; ml++)
        #pragma unroll
        for (int nt = 0; nt < 7; nt++)
            #pragma unroll
            for (int q = 0; q < 4; q++) c[ml][nt][q] = 0.f;

    #pragma unroll
    for (int j = 0; j < 7; j++) {
        uint32_t wbase = sW + j*64*WP_STRB;
        #pragma unroll
        for (int kst = 0; kst < 2; kst++) {
            int kb = (kst*16 + (lane >> 4)*8) * 2;
            uint32_t a[2][4];
            #pragma unroll
            for (int ml = 0; ml < 2; ml++) {
                int mi = wpar + ml*2;
                ldmx4(a[ml], wbase + (mi*16 + (lane & 15))*WP_STRB + kb);
            }
            uint32_t bf[4][4];
            int kbb = (kst*16 + ((lane >> 3) & 1)*8) * 2;
            #pragma unroll
            for (int nb8 = 0; nb8 < 4; nb8++) {
                int trow = nb8*16 + (lane & 7) + ((lane >> 4) << 3) + 2*j;
                ldmx4(bf[nb8], sX + trow*XST_STRB + kbb);
            }
            #pragma unroll
            for (int ml = 0; ml < 2; ml++)
                #pragma unroll
                for (int nt = 0; nt < 7; nt++)
                    mma_f16(c[ml][nt], a[ml], &bf[nt >> 1][(nt & 1)*2]);
        }
    }

    int gr = lane >> 2, qc = (lane & 3)*2;
    __half* hout = &g_hh[(size_t)(n*NB + b)*HVEC];
    #pragma unroll
    for (int hf = 0; hf < 2; hf++) {
        int o = wpar*16 + gr + hf*8;
        float fb = fbs[o], gb = gbs[o];
        #pragma unroll
        for (int nt = 0; nt < 7; nt++) {
            int t = nt*8 + qc;
            if (t < NK) {
                float h0 = fast_tanh(c[0][nt][hf*2+0] + fb) * fast_sig(c[1][nt][hf*2+0] + gb);
                float h1 = fast_tanh(c[0][nt][hf*2+1] + fb) * fast_sig(c[1][nt][hf*2+1] + gb);
                *(__half2*)&hout[o*NK + t] = __floats2half2_rn(h0, h1);
            }
        }
    }
}

// ---------------- fp16 HMMA A^2: B2 = fp16(0.9025*Ah@Ah + 0.0475*A + 0.05*I) ----------------
#define PA_STRB 144
#define PA_BYTES (128*PA_STRB)     // 18432
#define PB_STRB 272
#define PB_BYTES (64*PB_STRB)      // 17408
#define PBUF (PA_BYTES + PB_BYTES) // 35840
#define PROP_SMEM (3*PBUF)
__global__ __launch_bounds__(256,2) void asq_mma()
{
    extern __shared__ __align__(16) char smp[];
    int side = blockIdx.z;
    const __half* Ah = g_Ah[side];
    const float* Af = side ? g_a2f : g_a1f;
    __half* B2 = g_B2h[side];

    int tid = threadIdx.x, warp = tid >> 5, lane = tid & 31;
    int nbase = blockIdx.x * 128;     // output column tile
    int vt = blockIdx.y;              // output row tile
    int wm = (warp >> 2)*64, wn = (warp & 3)*32;
    uint32_t sb = smem_u32(smp);

    float c[4][4][4];
    #pragma unroll
    for (int i = 0; i < 4; i++)
        #pragma unroll
        for (int j = 0; j < 4; j++)
            #pragma unroll
            for (int q = 0; q < 4; q++) c[i][j][q] = 0.f;

    auto load_chunk = [&](int ch) {
        int buf = ch % 3;
        int w0 = ch * 64;
        uint32_t sA = sb + buf*PBUF;
        uint32_t sB = sA + PA_BYTES;
        #pragma unroll
        for (int j = 0; j < 4; j++) {
            int lin = tid + j*256;
            int r = lin >> 3, q = lin & 7;
            CP_ASYNC16(sA + r*PA_STRB + q*16, &Ah[(vt*128 + r)*VP + w0 + q*8]);
        }
        #pragma unroll
        for (int j = 0; j < 4; j++) {
            int lin = tid + j*256;
            int r = lin >> 4, q = lin & 15;
            CP_ASYNC16(sB + r*PB_STRB + q*16, &Ah[(size_t)(w0 + r)*VP + nbase + q*8]);
        }
        CP_COMMIT();
    };

    load_chunk(0);
    load_chunk(1);

    for (int ch = 0; ch < 8; ch++) {
        if (ch == 7) { CP_WAIT0(); } else { CP_WAIT1(); }
        __syncthreads();
        if (ch + 2 < 8) load_chunk(ch + 2);
        uint32_t sA = sb + (ch % 3)*PBUF;
        uint32_t sB = sA + PA_BYTES;
        #pragma unroll
        for (int ks = 0; ks < 4; ks++) {
            int k0 = ks * 16;
            uint32_t a[4][4];
            #pragma unroll
            for (int mi = 0; mi < 4; mi++)
                ldmx4(a[mi], sA + (wm + mi*16 + (lane & 15))*PA_STRB + (k0 + (lane >> 4)*8)*2);
            uint32_t bfr[2][4];
            #pragma unroll
            for (int np = 0; np < 2; np++)
                ldmx4t(bfr[np], sB + (k0 + (lane & 15))*PB_STRB + (wn + np*16 + (lane >> 4)*8)*2);
            #pragma unroll
            for (int mi = 0; mi < 4; mi++)
                #pragma unroll
                for (int ni = 0; ni < 4; ni++)
                    mma_f16(c[mi][ni], a[mi], &bfr[ni >> 1][(ni & 1)*2]);
        }
    }

    int gr = lane >> 2, qc = (lane & 3)*2;
    #pragma unroll
    for (int mi = 0; mi < 4; mi++) {
        #pragma unroll
        for (int hf = 0; hf < 2; hf++) {
            int v = vt*128 + wm + mi*16 + gr + hf*8;
            #pragma unroll
            for (int ni = 0; ni < 4; ni++) {
                int col = nbase + wn + ni*8 + qc;
                float2 af = *(const float2*)&Af[(size_t)v*VP + col];
                float v0 = 0.9025f*c[mi][ni][hf*2+0] + 0.0475f*af.x
                         + ((v == col && v < NV) ? 0.05f : 0.f);
                float v1 = 0.9025f*c[mi][ni][hf*2+1] + 0.0475f*af.y
                         + ((v == col+1 && v < NV) ? 0.05f : 0.f);
                *(__half2*)&B2[(size_t)v*VP + col] = __floats2half2_rn(v0, v1);
            }
        }
    }
}

// ---------------- skip conv as per-node HMMA GEMM (3-stage pipeline, race-free) ----------------
#define SK_WBYTES (64*272)
#define SK_BBYTES (32*272)
#define SK_BUF (SK_WBYTES + SK_BBYTES)
#define SKIP_SMEM (3*SK_BUF)
__global__ __launch_bounds__(128) void skip_mma(const float* __restrict__ skipb,
                                                float* __restrict__ sout)
{
    extern __shared__ __align__(16) char sks[];
    int n = blockIdx.x;
    int tid = threadIdx.x, warp = tid >> 5, lane = tid & 31;
    int m0 = warp * 16;
    uint32_t sb = smem_u32(sks);

    const __half* Bg = &g_hh[(size_t)n*NMCOL];

    float c[4][4];
    #pragma unroll
    for (int i = 0; i < 4; i++)
        #pragma unroll
        for (int j = 0; j < 4; j++) c[i][j] = 0.f;

    auto load_chunk = [&](int ch) {
        int buf = ch % 3;
        int k0 = ch * 128;
        uint32_t sW = sb + buf*SK_BUF;
        uint32_t sB = sW + SK_WBYTES;
        #pragma unroll
        for (int j = 0; j < 8; j++) {
            int lin = tid + j*128;
            int r = lin >> 4, q = lin & 15;
            CP_ASYNC16(sW + r*272 + q*16, &g_swh[r*HVEC + k0 + q*8]);
        }
        #pragma unroll
        for (int j = 0; j < 4; j++) {
            int lin = tid + j*128;
            int r = lin >> 4, q = lin & 15;
            CP_ASYNC16(sB + r*272 + q*16, &Bg[r*HVEC + k0 + q*8]);
        }
        CP_COMMIT();
    };

    load_chunk(0);
    load_chunk(1);

    for (int ch = 0; ch < 13; ch++) {
        if (ch == 12) { CP_WAIT0(); } else { CP_WAIT1(); }
        __syncthreads();
        if (ch + 2 < 13) load_chunk(ch + 2);
        uint32_t sW = sb + (ch % 3)*SK_BUF;
        uint32_t sB = sW + SK_WBYTES;
        #pragma unroll
        for (int ks = 0; ks < 8; ks++) {
            int k0 = ks * 16;
            uint32_t a[4];
            ldmx4(a, sW + (m0 + (lane & 15))*272 + (k0 + (lane >> 4)*8)*2);
            uint32_t bfr[2][4];
            #pragma unroll
            for (int np = 0; np < 2; np++)
                ldmx4(bfr[np], sB + (np*16 + (lane & 7) + ((lane >> 4) << 3))*272
                               + (k0 + ((lane >> 3) & 1)*8)*2);
            #pragma unroll
            for (int ni = 0; ni < 4; ni++)
                mma_f16(c[ni], a, &bfr[ni >> 1][(ni & 1)*2]);
        }
    }

    int gr = lane >> 2, qc = (lane & 3)*2;
    #pragma unroll
    for (int ni = 0; ni < 4; ni++) {
        int b0 = ni*8 + qc;
        int cs0 = m0 + gr;
        float bi0 = skipb[cs0], bi1 = skipb[cs0 + 8];
        sout[(b0*C_S + cs0)*NV + n]       = c[ni][0] + bi0;
        sout[((b0+1)*C_S + cs0)*NV + n]   = c[ni][1] + bi0;
        sout[(b0*C_S + cs0+8)*NV + n]     = c[ni][2] + bi1;
        sout[((b0+1)*C_S + cs0+8)*NV + n] = c[ni][3] + bi1;
    }
}

// ---------------- single-launch fp16 HMMA prop (BK=64, 3-stage, race-free) ----------------
__global__ __launch_bounds__(256,2) void prop_mma()
{
    extern __shared__ __align__(16) char smp[];
    int z = blockIdx.z;
    int side = z >> 1, which = z & 1;
    const __half* Aadj = which ? g_B2h[side] : g_B1h[side];
    const __half* Bin = g_hh;
    __half* Hout = (z == 0) ? g_h1ah : (z == 1) ? g_h2ah : (z == 2) ? g_h1bh : g_h2bh;

    int tid = threadIdx.x, warp = tid >> 5, lane = tid & 31;
    int nbase = blockIdx.x * 128;
    int vt = blockIdx.y;
    int wm = (warp >> 2)*64, wn = (warp & 3)*32;
    uint32_t sb = smem_u32(smp);

    float c[4][4][4];
    #pragma unroll
    for (int i = 0; i < 4; i++)
        #pragma unroll
        for (int j = 0; j < 4; j++)
            #pragma unroll
            for (int q = 0; q < 4; q++) c[i][j][q] = 0.f;

    auto load_chunk = [&](int ch) {
        int buf = ch % 3;
        int w0 = ch * 64;
        uint32_t sA = sb + buf*PBUF;
        uint32_t sB = sA + PA_BYTES;
        #pragma unroll
        for (int j = 0; j < 4; j++) {
            int lin = tid + j*256;
            int r = lin >> 3, q = lin & 7;
            CP_ASYNC16(sA + r*PA_STRB + q*16, &Aadj[(vt*128 + r)*VP + w0 + q*8]);
        }
        #pragma unroll
        for (int j = 0; j < 4; j++) {
            int lin = tid + j*256;
            int r = lin >> 4, q = lin & 15;
            CP_ASYNC16(sB + r*PB_STRB + q*16, &Bin[(size_t)(w0 + r)*NMCOL + nbase + q*8]);
        }
        CP_COMMIT();
    };

    load_chunk(0);
    load_chunk(1);

    for (int ch = 0; ch < 8; ch++) {
        if (ch == 7) { CP_WAIT0(); } else { CP_WAIT1(); }
        __syncthreads();
        if (ch + 2 < 8) load_chunk(ch + 2);
        uint32_t sA = sb + (ch % 3)*PBUF;
        uint32_t sB = sA + PA_BYTES;
        #pragma unroll
        for (int ks = 0; ks < 4; ks++) {
            int k0 = ks * 16;
            uint32_t a[4][4];
            #pragma unroll
            for (int mi = 0; mi < 4; mi++)
                ldmx4(a[mi], sA + (wm + mi*16 + (lane & 15))*PA_STRB + (k0 + (lane >> 4)*8)*2);
            uint32_t bfr[2][4];
            #pragma unroll
            for (int np = 0; np < 2; np++)
                ldmx4t(bfr[np], sB + (k0 + (lane & 15))*PB_STRB + (wn + np*16 + (lane >> 4)*8)*2);
            #pragma unroll
            for (int mi = 0; mi < 4; mi++)
                #pragma unroll
                for (int ni = 0; ni < 4; ni++)
                    mma_f16(c[mi][ni], a[mi], &bfr[ni >> 1][(ni & 1)*2]);
        }
    }

    int gr = lane >> 2, qc = (lane & 3)*2;
    #pragma unroll
    for (int mi = 0; mi < 4; mi++) {
        #pragma unroll
        for (int hf = 0; hf < 2; hf++) {
            int v = vt*128 + wm + mi*16 + gr + hf*8;
            if (v < NV) {
                #pragma unroll
                for (int ni = 0; ni < 4; ni++) {
                    size_t off = (size_t)v*NMCOL + nbase + wn + ni*8 + qc;
                    *(__half2*)&Hout[off] =
                        __floats2half2_rn(c[mi][ni][hf*2+0], c[mi][ni][hf*2+1]);
                }
            }
        }
    }
}

// ---------------- combine as per-(v,b) HMMA GEMM: out[c][l] = W[32x160] @ T[160x52] ----------------
#define CW_STRB 336
#define CW_BYTES (32*CW_STRB)              // 10752
#define CT_STRB 144
#define CT_WARP (160*CT_STRB)              // 23040 per warp
#define COMB_SMEM (CW_BYTES + 128 + 4*CT_WARP)
__global__ __launch_bounds__(128,2) void combine_mma(const float* __restrict__ x,
                                                     const float* __restrict__ gc1w,
                                                     const float* __restrict__ gc1b,
                                                     const float* __restrict__ gc2w,
                                                     const float* __restrict__ gc2b)
{
    extern __shared__ __align__(16) char smc[];
    uint32_t sW = smem_u32(smc);
    float* bias = (float*)(smc + CW_BYTES);
    uint32_t sT0 = sW + CW_BYTES + 128;

    int tid = threadIdx.x, warp = tid >> 5, lane = tid & 31;

    for (int e = tid; e < 5120; e += 128) {
        int cch = e / 160, k = e % 160;
        int t = k >> 5, cp = k & 31;
        float val;
        if      (t == 0) val = gc1w[cch*96 + cp] + gc2w[cch*96 + cp];
        else if (t == 1) val = gc1w[cch*96 + 32 + cp];
        else if (t == 2) val = gc1w[cch*96 + 64 + cp];
        else if (t == 3) val = gc2w[cch*96 + 32 + cp];
        else             val = gc2w[cch*96 + 64 + cp];
        *(__half*)(smc + cch*CW_STRB + k*2) = __float2half_rn(val);
    }
    if (tid < 32) bias[tid] = gc1b[tid] + gc2b[tid];

    int p = blockIdx.x * 4 + warp;
    int n = p >> 5, b = p & 31;
    uint32_t sT = sT0 + warp*CT_WARP;
    size_t slab_off = (size_t)(n*NB + b)*HVEC;
    for (int e = lane; e < 160*13; e += 32) {
        int r = e / 13, j = e % 13;
        const __half* slab = (r < 32) ? g_hh : (r < 64) ? g_h1ah : (r < 96) ? g_h2ah
                            : (r < 128) ? g_h1bh : g_h2bh;
        uint2 v = *(const uint2*)&slab[slab_off + (size_t)(r & 31)*NK + j*4];
        *(uint2*)((char*)smc + (sT - smem_u32(smc)) + r*CT_STRB + j*8) = v;
    }
    __syncthreads();

    float c[2][7][4];
    #pragma unroll
    for (int mi = 0; mi < 2; mi++)
        #pragma unroll
        for (int nt = 0; nt < 7; nt++)
            #pragma unroll
            for (int q = 0; q < 4; q++) c[mi][nt][q] = 0.f;

    #pragma unroll
    for (int ks = 0; ks < 10; ks++) {
        int k0 = ks * 16;
        uint32_t a[2][4];
        #pragma unroll
        for (int mi = 0; mi < 2; mi++)
            ldmx4(a[mi], sW + (mi*16 + (lane & 15))*CW_STRB + (k0 + (lane >> 4)*8)*2);
        uint32_t bq[4][4];
        #pragma unroll
        for (int nq = 0; nq < 4; nq++)
            ldmx4t(bq[nq], sT + (k0 + (lane & 15))*CT_STRB + (nq*16 + (lane >> 4)*8)*2);
        #pragma unroll
        for (int mi = 0; mi < 2; mi++)
            #pragma unroll
            for (int nt = 0; nt < 7; nt++)
                mma_f16(c[mi][nt], a[mi], &bq[nt >> 1][(nt & 1)*2]);
    }

    int gr = lane >> 2, qc = (lane & 3)*2;
    float psum = 0.f, psq = 0.f;
    #pragma unroll
    for (int mi = 0; mi < 2; mi++) {
        #pragma unroll
        for (int hf = 0; hf < 2; hf++) {
            int cch = mi*16 + gr + hf*8;
            float bi = bias[cch];
            const float* xr = &x[((size_t)(b*C_R + cch)*NV + n)*NT + 12];
            __half* xoh = &g_xoh[((size_t)(b*C_C + cch)*NV + n)*NK];
            #pragma unroll
            for (int nt = 0; nt < 7; nt++) {
                int l = nt*8 + qc;
                if (l < NK) {
                    float v0 = c[mi][nt][hf*2+0] + bi + xr[l];
                    float v1 = c[mi][nt][hf*2+1] + bi + xr[l+1];
                    *(__half2*)&xoh[l] = __floats2half2_rn(v0, v1);
                    psum += v0 + v1;
                    psq  = fmaf(v0, v0, psq);
                    psq  = fmaf(v1, v1, psq);
                }
            }
        }
    }
    #pragma unroll
    for (int off = 16; off > 0; off >>= 1) {
        psum += __shfl_down_sync(0xffffffffu, psum, off);
        psq  += __shfl_down_sync(0xffffffffu, psq,  off);
    }
    if (lane == 0) {
        atomicAdd(&g_stats[2*b], psum);
        atomicAdd(&g_stats[2*b + 1], psq);
    }
}

// ---------------- LayerNorm apply (reads fp16 xo) ----------------
__global__ __launch_bounds__(256) void norm_kernel(const int* __restrict__ idx,
                                                   const float* __restrict__ lnw,
                                                   const float* __restrict__ lnb,
                                                   float* __restrict__ out)
{
    int gid = blockIdx.x * 256 + threadIdx.x;
    int lq = gid % 13;
    int row = gid / 13;
    int v = row % NV;
    int cch = (row / NV) % C_C;
    int b = row / (C_C*NV);

    float s1 = g_stats[2*b], s2 = g_stats[2*b + 1];
    float mean = s1 * (1.f/(float)CNT_PER_B);
    float var  = s2 * (1.f/(float)CNT_PER_B) - mean*mean;
    float rstd = rsqrtf(var + 1e-5f);
    int nidx = idx[v];

    uint2 raw = *(const uint2*)&g_xoh[(size_t)row*NK + lq*4];
    float2 f01 = __half22float2(*(__half2*)&raw.x);
    float2 f23 = __half22float2(*(__half2*)&raw.y);
    float4 w4 = *(const float4*)&lnw[(cch*NV + nidx)*NK + lq*4];
    float4 b4 = *(const float4*)&lnb[(cch*NV + nidx)*NK + lq*4];
    float4 o;
    o.x = (f01.x - mean)*rstd*w4.x + b4.x;
    o.y = (f01.y - mean)*rstd*w4.y + b4.y;
    o.z = (f23.x - mean)*rstd*w4.z + b4.z;
    o.w = (f23.y - mean)*rstd*w4.w + b4.w;
    *(float4*)&out[row*NK + lq*4] = o;
}

// ---------------- launch (forked capture: side stream for adj chain + skip) ----------------
extern "C" void kernel_launch(void* const* d_in, const int* in_sizes, int n_in,
                              void* d_out, int out_size)
{
    const float* x = (const float*)d_in[0];
    int ia = (in_sizes[1] == NV*NV) ? 1 : 2;
    const float* adp = (const float*)d_in[ia];
    const int*   idx = (const int*)d_in[3 - ia];
    const float* fw2 = (const float*)d_in[3];
    const float* fb2 = (const float*)d_in[4];
    const float* fw3 = (const float*)d_in[5];
    const float* fb3 = (const float*)d_in[6];
    const float* fw6 = (const float*)d_in[7];
    const float* fb6 = (const float*)d_in[8];
    const float* fw7 = (const float*)d_in[9];
    const float* fb7 = (const float*)d_in[10];
    const float* gw2 = (const float*)d_in[11];
    const float* gb2 = (const float*)d_in[12];
    const float* gw3 = (const float*)d_in[13];
    const float* gb3 = (const float*)d_in[14];
    const float* gw6 = (const float*)d_in[15];
    const float* gb6 = (const float*)d_in[16];
    const float* gw7 = (const float*)d_in[17];
    const float* gb7 = (const float*)d_in[18];
    const float* skipw = (const float*)d_in[19];
    const float* skipb = (const float*)d_in[20];
    const float* gc1w = (const float*)d_in[21];
    const float* gc1b = (const float*)d_in[22];
    const float* gc2w = (const float*)d_in[23];
    const float* gc2b = (const float*)d_in[24];
    const float* lnw = (const float*)d_in[25];
    const float* lnb = (const float*)d_in[26];
    float* out = (float*)d_out;
    float* s_out = out + NB*C_C*NV*NK;

    static cudaStream_t s_side = nullptr;
    static cudaEvent_t evFork = nullptr, evAdj = nullptr, evH = nullptr, evSkip = nullptr;
    if (s_side == nullptr) {
        cudaStreamCreateWithFlags(&s_side, cudaStreamNonBlocking);
        cudaEventCreateWithFlags(&evFork, cudaEventDisableTiming);
        cudaEventCreateWithFlags(&evAdj,  cudaEventDisableTiming);
        cudaEventCreateWithFlags(&evH,    cudaEventDisableTiming);
        cudaEventCreateWithFlags(&evSkip, cudaEventDisableTiming);
        cudaFuncSetAttribute(incept_mma,  cudaFuncAttributeMaxDynamicSharedMemorySize, INCEPT_SMEM);
        cudaFuncSetAttribute(skip_mma,    cudaFuncAttributeMaxDynamicSharedMemorySize, SKIP_SMEM);
        cudaFuncSetAttribute(asq_mma,     cudaFuncAttributeMaxDynamicSharedMemorySize, PROP_SMEM);
        cudaFuncSetAttribute(prop_mma,    cudaFuncAttributeMaxDynamicSharedMemorySize, PROP_SMEM);
        cudaFuncSetAttribute(combine_mma, cudaFuncAttributeMaxDynamicSharedMemorySize, COMB_SMEM);
    }

    // fork side stream from capture origin
    cudaEventRecord(evFork, 0);
    cudaStreamWaitEvent(s_side, evFork, 0);

    // side: adjacency chain (independent of pack/incept)
    zerocs_kernel<<<2, 256, 0, s_side>>>();
    sums_kernel<<<NV, 256, 0, s_side>>>(adp);
    buildAB_kernel<<<dim3(16, 16), 256, 0, s_side>>>(adp);
    asq_mma<<<dim3(4, 4, 2), 256, PROP_SMEM, s_side>>>();
    cudaEventRecord(evAdj, s_side);

    // main: weights pack, inception
    pack_kernel<<<64, 256>>>(fw2, fw3, fw6, fw7, fb2, fb3, fb6, fb7,
                             gw2, gw3, gw6, gw7, gb2, gb3, gb6, gb7, skipw);
    incept_mma<<<4000, 256, INCEPT_SMEM>>>(x);
    cudaEventRecord(evH, 0);

    // side: skip conv (needs h) runs concurrently with prop
    cudaStreamWaitEvent(s_side, evH, 0);
    skip_mma<<<NV, 128, SKIP_SMEM, s_side>>>(skipb, s_out);
    cudaEventRecord(evSkip, s_side);

    // main: prop (needs B1/B2 + h), combine, norm
    cudaStreamWaitEvent(0, evAdj, 0);
    prop_mma<<<dim3(NMCOL/128, 4, 4), 256, PROP_SMEM>>>();
    combine_mma<<<4000, 128, COMB_SMEM>>>(x, gc1w, gc1b, gc2w, gc2b);
    cudaStreamWaitEvent(0, evSkip, 0);
    norm_kernel<<<26000, 256>>>(idx, lnw, lnb, out);
}